// round 9
// baseline (speedup 1.0000x reference)
#include <cuda_runtime.h>
#include <cstdint>

// 2-bit quantized embedding gather — R9: 16 tokens per warp.
// input_ids: [262144] int32 ; bit_arr: [3.2M] int32 ; codebook: [4] fp32
// out: [262144, 128] fp32.
//
// pos = token*128 + dim, bitpos = pos*2 -> each token's 128 codes are an
// aligned 8-word (32B) block at word token*8. Lane t handles dims 4t..4t+3
// = byte t of that block.
//
// R8 ncu: DRAM 47.5%, L2 51.5%, L1 61.3%, issue 32.6% -> still
// concurrency-limited. This version: 4 independent int4 id loads, 16
// independent bits loads (MLP=16, 32-bit offsets to contain reg pressure),
// 16 independent 512B coalesced streaming stores.

#define TOK_PER_WARP 16

__global__ __launch_bounds__(256)
void embed2bit_kernel(const int4* __restrict__ ids4,
                      const unsigned int* __restrict__ bits,
                      const float* __restrict__ cb,
                      float4* __restrict__ out,
                      int n_tokens)
{
    int warp = (blockIdx.x * blockDim.x + threadIdx.x) >> 5;
    int lane = threadIdx.x & 31;

    int tok_base = warp * TOK_PER_WARP;
    if (tok_base >= n_tokens) return;

    // Four independent warp-uniform 16B loads = 16 token ids.
    int4 t0 = __ldg(&ids4[warp * 4 + 0]);
    int4 t1 = __ldg(&ids4[warp * 4 + 1]);
    int4 t2 = __ldg(&ids4[warp * 4 + 2]);
    int4 t3 = __ldg(&ids4[warp * 4 + 3]);

    // 32-bit word offsets: tok*8 + lane/4 (max 3.2M, fits u32 -> fewer regs).
    unsigned int wsel = (unsigned int)(lane >> 2);
    unsigned int off[TOK_PER_WARP];
    off[ 0] = (unsigned int)t0.x * 8u + wsel;
    off[ 1] = (unsigned int)t0.y * 8u + wsel;
    off[ 2] = (unsigned int)t0.z * 8u + wsel;
    off[ 3] = (unsigned int)t0.w * 8u + wsel;
    off[ 4] = (unsigned int)t1.x * 8u + wsel;
    off[ 5] = (unsigned int)t1.y * 8u + wsel;
    off[ 6] = (unsigned int)t1.z * 8u + wsel;
    off[ 7] = (unsigned int)t1.w * 8u + wsel;
    off[ 8] = (unsigned int)t2.x * 8u + wsel;
    off[ 9] = (unsigned int)t2.y * 8u + wsel;
    off[10] = (unsigned int)t2.z * 8u + wsel;
    off[11] = (unsigned int)t2.w * 8u + wsel;
    off[12] = (unsigned int)t3.x * 8u + wsel;
    off[13] = (unsigned int)t3.y * 8u + wsel;
    off[14] = (unsigned int)t3.z * 8u + wsel;
    off[15] = (unsigned int)t3.w * 8u + wsel;

    // 16 independent code-block loads in flight (MLP=16).
    unsigned int w[TOK_PER_WARP];
    #pragma unroll
    for (int j = 0; j < TOK_PER_WARP; j++)
        w[j] = __ldg(&bits[off[j]]);

    // Codebook in registers; decode via predicated selects, no memory LUT.
    float c0 = __ldg(&cb[0]);
    float c1 = __ldg(&cb[1]);
    float c2 = __ldg(&cb[2]);
    float c3 = __ldg(&cb[3]);

    #define DECODE(c) (((c) & 1u) ? (((c) & 2u) ? c3 : c1) \
                                  : (((c) & 2u) ? c2 : c0))
    unsigned int sel = lane & 3;   // which byte of the word this lane owns
    float4* obase = out + (size_t)tok_base * 32 + lane;

    #pragma unroll
    for (int j = 0; j < TOK_PER_WARP; j++) {
        unsigned int byte = __byte_perm(w[j], 0u, sel) & 0xFFu;  // 1 PRMT
        float4 v;
        v.x = DECODE(((byte >> 0) & 3u));
        v.y = DECODE(((byte >> 2) & 3u));
        v.z = DECODE(((byte >> 4) & 3u));
        v.w = DECODE(((byte >> 6) & 3u));
        // 512 B fully-coalesced streaming store (write-once: bypass L2 residency).
        __stcs(obase + j * 32, v);
    }
    #undef DECODE
}

extern "C" void kernel_launch(void* const* d_in, const int* in_sizes, int n_in,
                              void* d_out, int out_size)
{
    const int4*         ids4 = (const int4*)d_in[0];
    const unsigned int* bits = (const unsigned int*)d_in[1];
    const float*        cb   = (const float*)d_in[2];
    float4*             out  = (float4*)d_out;

    int n_tokens = in_sizes[0];                       // 262144 (divisible by 16)
    int warps = (n_tokens + TOK_PER_WARP - 1) / TOK_PER_WARP;
    int threads = 256;                                // 8 warps/block
    int blocks = (warps + 7) / 8;

    embed2bit_kernel<<<blocks, threads>>>(ids4, bits, cb, out, n_tokens);
}